// round 1
// baseline (speedup 1.0000x reference)
#include <cuda_runtime.h>

#define EMBED 256
#define HEADS 4
#define HDIM  64
#define BATCH 4
#define SQL   512
#define SKL   512
#define MTOT  (BATCH*SQL)   /* 2048 */

// Scratch (allocation-free rule: __device__ globals)
__device__ float g_Q[MTOT*EMBED];
__device__ float g_K[MTOT*EMBED];
__device__ float g_V[MTOT*EMBED];
__device__ float g_att[MTOT*EMBED];

__device__ __forceinline__ float fast_tanh(float x) {
    float y;
    asm("tanh.approx.f32 %0, %1;" : "=f"(y) : "f"(x));
    return y;
}

// ---------------------------------------------------------------------------
// C[M,N] = A[M,K] @ W[N,K]^T + bias[N]   (torch Linear semantics)
// 64x64 tile, BK=16, 256 threads, 4x4 micro-tile per thread.
// ---------------------------------------------------------------------------
__global__ __launch_bounds__(256) void gemm_bias_kernel(
    const float* __restrict__ A, const float* __restrict__ W,
    const float* __restrict__ bias, float* __restrict__ C,
    int M, int N, int K)
{
    __shared__ float As[16][68];
    __shared__ float Ws[16][68];
    const int tid = threadIdx.x;
    const int tx  = tid & 15;        // n direction
    const int ty  = tid >> 4;        // m direction
    const int n0  = blockIdx.x * 64;
    const int m0  = blockIdx.y * 64;

    const int lr = tid >> 2;          // 0..63 row in tile
    const int lc = (tid & 3) << 2;    // 0,4,8,12 k offset
    const float* Ag = A + (size_t)(m0 + lr) * K + lc;
    const float* Wg = W + (size_t)(n0 + lr) * K + lc;

    float a00=0,a01=0,a02=0,a03=0, a10=0,a11=0,a12=0,a13=0;
    float a20=0,a21=0,a22=0,a23=0, a30=0,a31=0,a32=0,a33=0;

    for (int k0 = 0; k0 < K; k0 += 16) {
        float4 av = *(const float4*)(Ag + k0);
        float4 wv = *(const float4*)(Wg + k0);
        As[lc+0][lr] = av.x; As[lc+1][lr] = av.y; As[lc+2][lr] = av.z; As[lc+3][lr] = av.w;
        Ws[lc+0][lr] = wv.x; Ws[lc+1][lr] = wv.y; Ws[lc+2][lr] = wv.z; Ws[lc+3][lr] = wv.w;
        __syncthreads();
        #pragma unroll
        for (int k = 0; k < 16; k++) {
            float4 a = *(const float4*)&As[k][ty*4];
            float4 w = *(const float4*)&Ws[k][tx*4];
            a00 += a.x*w.x; a01 += a.x*w.y; a02 += a.x*w.z; a03 += a.x*w.w;
            a10 += a.y*w.x; a11 += a.y*w.y; a12 += a.y*w.z; a13 += a.y*w.w;
            a20 += a.z*w.x; a21 += a.z*w.y; a22 += a.z*w.z; a23 += a.z*w.w;
            a30 += a.w*w.x; a31 += a.w*w.y; a32 += a.w*w.z; a33 += a.w*w.w;
        }
        __syncthreads();
    }

    const float4 bb = *(const float4*)&bias[n0 + tx*4];
    float* Cp = C + (size_t)(m0 + ty*4) * N + n0 + tx*4;
    float4 o;
    o.x=a00+bb.x; o.y=a01+bb.y; o.z=a02+bb.z; o.w=a03+bb.w; *(float4*)(Cp)       = o;
    o.x=a10+bb.x; o.y=a11+bb.y; o.z=a12+bb.z; o.w=a13+bb.w; *(float4*)(Cp + N)   = o;
    o.x=a20+bb.x; o.y=a21+bb.y; o.z=a22+bb.z; o.w=a23+bb.w; *(float4*)(Cp + 2*N) = o;
    o.x=a30+bb.x; o.y=a31+bb.y; o.z=a32+bb.z; o.w=a33+bb.w; *(float4*)(Cp + 3*N) = o;
}

// ---------------------------------------------------------------------------
// Fused additive-attention kernel.
// Block = (b, h, 16 q-rows). Computes scores (tanh/MUFU), softmax, attn write,
// and attn @ V into g_att.
// Dynamic smem layout (floats):
//   Qs   [16*64]     = 1024
//   vs   [64]        = 64
//   sc   [16*516]    = 8256   (pitch 516 -> bank-stride 4)
//   kv   [8704]      = max(K-transposed 64*129=8256, V chunk 128*68=8704)
// total 18048 floats = 72192 bytes
// ---------------------------------------------------------------------------
#define SC_PITCH 516
#define ATTN_SMEM_FLOATS (1024 + 64 + 16*SC_PITCH + 8704)

__global__ __launch_bounds__(256) void attn_kernel(
    const float* __restrict__ vparam, float* __restrict__ attn_out)
{
    extern __shared__ float smem[];
    float* Qs = smem;                    // [16][64]
    float* vs = Qs + 1024;               // [64]
    float* sc = vs + 64;                 // [16][516]
    float* kv = sc + 16*SC_PITCH;        // union K-chunk / V-chunk

    const int tid  = threadIdx.x;
    const int lane = tid & 31;
    const int warp = tid >> 5;
    const int b  = blockIdx.z;
    const int h  = blockIdx.y;
    const int q0 = blockIdx.x << 4;

    // stage v[h,:] and the 16 Q rows
    if (tid < 64) vs[tid] = vparam[h*HDIM + tid];
    {
        int q  = tid >> 4;
        int dg = (tid & 15) << 2;
        float4 t = *(const float4*)&g_Q[((size_t)(b*SQL + q0 + q))*EMBED + h*HDIM + dg];
        *(float4*)&Qs[q*64 + dg] = t;
    }
    __syncthreads();

    const float scale = 0.125f;   // 1/sqrt(64)

    // ------------ scores: 4 chunks of 128 k-rows ------------
    for (int c = 0; c < 4; c++) {
        // load K chunk transposed: kv[d*129 + kp]
        for (int i = tid; i < 128*16; i += 256) {
            int kp = i >> 4;
            int dg = (i & 15) << 2;
            float4 t = *(const float4*)&g_K[((size_t)(b*SKL + c*128 + kp))*EMBED + h*HDIM + dg];
            kv[(dg+0)*129 + kp] = t.x;
            kv[(dg+1)*129 + kp] = t.y;
            kv[(dg+2)*129 + kp] = t.z;
            kv[(dg+3)*129 + kp] = t.w;
        }
        __syncthreads();

        #pragma unroll
        for (int qq = 0; qq < 2; qq++) {
            const int q = warp*2 + qq;
            const float* qrow = &Qs[q*64];
            float s0=0.f, s1=0.f, s2=0.f, s3=0.f;
            #pragma unroll 8
            for (int d = 0; d < 64; d++) {
                float qd = qrow[d];
                float vd = vs[d];
                const float* kr = &kv[d*129];
                s0 += vd * fast_tanh(qd + kr[lane]);
                s1 += vd * fast_tanh(qd + kr[lane + 32]);
                s2 += vd * fast_tanh(qd + kr[lane + 64]);
                s3 += vd * fast_tanh(qd + kr[lane + 96]);
            }
            float* srow = &sc[q*SC_PITCH + c*128];
            srow[lane]      = s0 * scale;
            srow[lane + 32] = s1 * scale;
            srow[lane + 64] = s2 * scale;
            srow[lane + 96] = s3 * scale;
        }
        __syncthreads();
    }

    // ------------ softmax (each warp: 2 rows of 512) ------------
    #pragma unroll
    for (int qq = 0; qq < 2; qq++) {
        const int q = warp*2 + qq;
        float* srow = &sc[q*SC_PITCH];
        float m = -1e30f;
        #pragma unroll
        for (int j = 0; j < 16; j++) m = fmaxf(m, srow[lane + 32*j]);
        #pragma unroll
        for (int o = 16; o; o >>= 1) m = fmaxf(m, __shfl_xor_sync(0xffffffffu, m, o));
        float e[16];
        float s = 0.f;
        #pragma unroll
        for (int j = 0; j < 16; j++) { e[j] = __expf(srow[lane + 32*j] - m); s += e[j]; }
        #pragma unroll
        for (int o = 16; o; o >>= 1) s += __shfl_xor_sync(0xffffffffu, s, o);
        const float r = 1.0f / s;
        float* arow = attn_out + ((size_t)((b*HEADS + h)*SQL + q0 + q))*SKL;
        #pragma unroll
        for (int j = 0; j < 16; j++) {
            float p = e[j] * r;
            srow[lane + 32*j] = p;
            arow[lane + 32*j] = p;
        }
    }
    __syncthreads();

    // ------------ attended = attn @ V ------------
    {
        const int q  = tid >> 4;
        const int dg = (tid & 15) << 2;
        float ax=0.f, ay=0.f, az=0.f, aw=0.f;
        for (int c = 0; c < 4; c++) {
            if (c) __syncthreads();
            for (int i = tid; i < 128*16; i += 256) {
                int kp = i >> 4;
                int d4 = (i & 15) << 2;
                float4 t = *(const float4*)&g_V[((size_t)(b*SKL + c*128 + kp))*EMBED + h*HDIM + d4];
                *(float4*)&kv[kp*68 + d4] = t;
            }
            __syncthreads();
            const float* prow = &sc[q*SC_PITCH + c*128];
            #pragma unroll 4
            for (int kp = 0; kp < 128; kp++) {
                float p = prow[kp];
                float4 vv = *(const float4*)&kv[kp*68 + dg];
                ax += p*vv.x; ay += p*vv.y; az += p*vv.z; aw += p*vv.w;
            }
        }
        float4 o; o.x=ax; o.y=ay; o.z=az; o.w=aw;
        *(float4*)&g_att[((size_t)(b*SQL + q0 + q))*EMBED + h*HDIM + dg] = o;
    }
}

// ---------------------------------------------------------------------------
extern "C" void kernel_launch(void* const* d_in, const int* in_sizes, int n_in,
                              void* d_out, int out_size)
{
    (void)in_sizes; (void)n_in; (void)out_size;
    const float* query = (const float*)d_in[0];
    const float* key_  = (const float*)d_in[1];
    const float* value = (const float*)d_in[2];
    const float* Wq = (const float*)d_in[3];
    const float* bq = (const float*)d_in[4];
    const float* Wk = (const float*)d_in[5];
    const float* bk = (const float*)d_in[6];
    const float* Wv = (const float*)d_in[7];
    const float* bv = (const float*)d_in[8];
    const float* vp = (const float*)d_in[9];
    const float* Wo = (const float*)d_in[10];
    const float* bo = (const float*)d_in[11];

    float* out  = (float*)d_out;                 // [B, SQ, EMBED]
    float* attn = out + (size_t)MTOT * EMBED;    // [B, H, SQ, SK]

    float *gQ, *gK, *gV, *gA;
    cudaGetSymbolAddress((void**)&gQ, g_Q);
    cudaGetSymbolAddress((void**)&gK, g_K);
    cudaGetSymbolAddress((void**)&gV, g_V);
    cudaGetSymbolAddress((void**)&gA, g_att);

    const int smem_bytes = ATTN_SMEM_FLOATS * (int)sizeof(float);
    cudaFuncSetAttribute(attn_kernel, cudaFuncAttributeMaxDynamicSharedMemorySize, smem_bytes);

    dim3 ggrid(EMBED/64, MTOT/64);   // (4, 32)
    gemm_bias_kernel<<<ggrid, 256>>>(query, Wq, bq, gQ, MTOT, EMBED, EMBED);
    gemm_bias_kernel<<<ggrid, 256>>>(key_,  Wk, bk, gK, MTOT, EMBED, EMBED);
    gemm_bias_kernel<<<ggrid, 256>>>(value, Wv, bv, gV, MTOT, EMBED, EMBED);

    dim3 agrid(SQL/16, HEADS, BATCH);  // (32, 4, 4)
    attn_kernel<<<agrid, 256, smem_bytes>>>(vp, attn);

    gemm_bias_kernel<<<ggrid, 256>>>(gA, Wo, bo, out, MTOT, EMBED, EMBED);
}

// round 2
// speedup vs baseline: 1.1539x; 1.1539x over previous
#include <cuda_runtime.h>

#define EMBED 256
#define HEADS 4
#define HDIM  64
#define BATCH 4
#define SQL   512
#define SKL   512
#define MTOT  (BATCH*SQL)   /* 2048 */

// Scratch (allocation-free rule: __device__ globals)
__device__ float g_Q[MTOT*EMBED];
__device__ float g_K[MTOT*EMBED];
__device__ float g_V[MTOT*EMBED];
__device__ float g_att[MTOT*EMBED];

__device__ __forceinline__ float fast_tanh(float x) {
    float y;
    asm("tanh.approx.f32 %0, %1;" : "=f"(y) : "f"(x));
    return y;
}

// ---------------------------------------------------------------------------
// C[M,N] = A[M,K] @ W[N,K]^T + bias[N]   (torch Linear semantics)
// 64x64 tile, BK=16, 256 threads, 4x4 micro-tile per thread.
// grid.z selects one of up to 3 independent (A,W,b,C) problems.
// ---------------------------------------------------------------------------
__global__ __launch_bounds__(256) void gemm_bias3_kernel(
    const float* __restrict__ A0, const float* __restrict__ A1, const float* __restrict__ A2,
    const float* __restrict__ W0, const float* __restrict__ W1, const float* __restrict__ W2,
    const float* __restrict__ b0, const float* __restrict__ b1, const float* __restrict__ b2,
    float* __restrict__ C0, float* __restrict__ C1, float* __restrict__ C2,
    int M, int N, int K)
{
    const float* A; const float* W; const float* bias; float* C;
    if (blockIdx.z == 0)      { A = A0; W = W0; bias = b0; C = C0; }
    else if (blockIdx.z == 1) { A = A1; W = W1; bias = b1; C = C1; }
    else                      { A = A2; W = W2; bias = b2; C = C2; }

    __shared__ float As[16][68];
    __shared__ float Ws[16][68];
    const int tid = threadIdx.x;
    const int tx  = tid & 15;        // n direction
    const int ty  = tid >> 4;        // m direction
    const int n0  = blockIdx.x * 64;
    const int m0  = blockIdx.y * 64;

    const int lr = tid >> 2;          // 0..63 row in tile
    const int lc = (tid & 3) << 2;    // 0,4,8,12 k offset
    const float* Ag = A + (size_t)(m0 + lr) * K + lc;
    const float* Wg = W + (size_t)(n0 + lr) * K + lc;

    float a00=0,a01=0,a02=0,a03=0, a10=0,a11=0,a12=0,a13=0;
    float a20=0,a21=0,a22=0,a23=0, a30=0,a31=0,a32=0,a33=0;

    for (int k0 = 0; k0 < K; k0 += 16) {
        float4 av = *(const float4*)(Ag + k0);
        float4 wv = *(const float4*)(Wg + k0);
        As[lc+0][lr] = av.x; As[lc+1][lr] = av.y; As[lc+2][lr] = av.z; As[lc+3][lr] = av.w;
        Ws[lc+0][lr] = wv.x; Ws[lc+1][lr] = wv.y; Ws[lc+2][lr] = wv.z; Ws[lc+3][lr] = wv.w;
        __syncthreads();
        #pragma unroll
        for (int k = 0; k < 16; k++) {
            float4 a = *(const float4*)&As[k][ty*4];
            float4 w = *(const float4*)&Ws[k][tx*4];
            a00 += a.x*w.x; a01 += a.x*w.y; a02 += a.x*w.z; a03 += a.x*w.w;
            a10 += a.y*w.x; a11 += a.y*w.y; a12 += a.y*w.z; a13 += a.y*w.w;
            a20 += a.z*w.x; a21 += a.z*w.y; a22 += a.z*w.z; a23 += a.z*w.w;
            a30 += a.w*w.x; a31 += a.w*w.y; a32 += a.w*w.z; a33 += a.w*w.w;
        }
        __syncthreads();
    }

    const float4 bb = *(const float4*)&bias[n0 + tx*4];
    float* Cp = C + (size_t)(m0 + ty*4) * N + n0 + tx*4;
    float4 o;
    o.x=a00+bb.x; o.y=a01+bb.y; o.z=a02+bb.z; o.w=a03+bb.w; *(float4*)(Cp)       = o;
    o.x=a10+bb.x; o.y=a11+bb.y; o.z=a12+bb.z; o.w=a13+bb.w; *(float4*)(Cp + N)   = o;
    o.x=a20+bb.x; o.y=a21+bb.y; o.z=a22+bb.z; o.w=a23+bb.w; *(float4*)(Cp + 2*N) = o;
    o.x=a30+bb.x; o.y=a31+bb.y; o.z=a32+bb.z; o.w=a33+bb.w; *(float4*)(Cp + 3*N) = o;
}

// ---------------------------------------------------------------------------
// Fused additive-attention kernel, v2.
// Block = (b, h, 16 q-rows), 256 threads (8 warps). Warp w owns q-rows 2w,2w+1.
// K/V staged k-major (no transpose) with pitch 68; chunk = 64 k-rows.
// Smem floats: Qs 1024 + vs 64 + sc 16*516 + kv 64*68 = 13696 (54784 B) -> 4 blocks/SM.
// ---------------------------------------------------------------------------
#define CK 64
#define NCH (SKL/CK)
#define SC_PITCH 516
#define KV_PITCH 68
#define ATTN_SMEM_FLOATS (1024 + 64 + 16*SC_PITCH + CK*KV_PITCH)

__global__ __launch_bounds__(256, 4) void attn_kernel(
    const float* __restrict__ vparam, float* __restrict__ attn_out)
{
    extern __shared__ float smem[];
    float* Qs = smem;                    // [16][64]
    float* vs = Qs + 1024;               // [64]
    float* sc = vs + 64;                 // [16][516]
    float* kv = sc + 16*SC_PITCH;        // [64][68]  K-chunk / V-chunk

    const int tid  = threadIdx.x;
    const int lane = tid & 31;
    const int warp = tid >> 5;
    const int b  = blockIdx.z;
    const int h  = blockIdx.y;
    const int q0t = blockIdx.x << 4;

    // stage v[h,:] and the 16 Q rows
    if (tid < 64) vs[tid] = vparam[h*HDIM + tid];
    {
        int q  = tid >> 4;
        int dg = (tid & 15) << 2;
        float4 t = *(const float4*)&g_Q[((size_t)(b*SQL + q0t + q))*EMBED + h*HDIM + dg];
        *(float4*)&Qs[q*64 + dg] = t;
    }
    __syncthreads();

    const float scale = 0.125f;   // 1/sqrt(64)
    const int qa = warp*2;        // this warp's two q rows
    const int qb = qa + 1;

    // ------------ scores: 8 chunks of 64 k-rows ------------
    for (int c = 0; c < NCH; c++) {
        // stage K chunk k-major: kv[kp*68 + d]
        #pragma unroll
        for (int it = 0; it < 4; it++) {
            int i  = tid + it*256;
            int kp = i >> 4;
            int dg = (i & 15) << 2;
            float4 t = *(const float4*)&g_K[((size_t)(b*SKL + c*CK + kp))*EMBED + h*HDIM + dg];
            *(float4*)&kv[kp*KV_PITCH + dg] = t;
        }
        __syncthreads();

        float s00=0.f, s01=0.f, s10=0.f, s11=0.f;
        const float* k0p = &kv[lane*KV_PITCH];
        const float* k1p = &kv[(lane+32)*KV_PITCH];
        #pragma unroll 4
        for (int d = 0; d < 64; d += 4) {
            float4 qav = *(const float4*)&Qs[qa*64 + d];
            float4 qbv = *(const float4*)&Qs[qb*64 + d];
            float4 vv  = *(const float4*)&vs[d];
            float4 k0  = *(const float4*)(k0p + d);
            float4 k1  = *(const float4*)(k1p + d);
            s00 += vv.x*fast_tanh(qav.x + k0.x);
            s00 += vv.y*fast_tanh(qav.y + k0.y);
            s00 += vv.z*fast_tanh(qav.z + k0.z);
            s00 += vv.w*fast_tanh(qav.w + k0.w);
            s01 += vv.x*fast_tanh(qav.x + k1.x);
            s01 += vv.y*fast_tanh(qav.y + k1.y);
            s01 += vv.z*fast_tanh(qav.z + k1.z);
            s01 += vv.w*fast_tanh(qav.w + k1.w);
            s10 += vv.x*fast_tanh(qbv.x + k0.x);
            s10 += vv.y*fast_tanh(qbv.y + k0.y);
            s10 += vv.z*fast_tanh(qbv.z + k0.z);
            s10 += vv.w*fast_tanh(qbv.w + k0.w);
            s11 += vv.x*fast_tanh(qbv.x + k1.x);
            s11 += vv.y*fast_tanh(qbv.y + k1.y);
            s11 += vv.z*fast_tanh(qbv.z + k1.z);
            s11 += vv.w*fast_tanh(qbv.w + k1.w);
        }
        sc[qa*SC_PITCH + c*CK + lane]      = s00 * scale;
        sc[qa*SC_PITCH + c*CK + lane + 32] = s01 * scale;
        sc[qb*SC_PITCH + c*CK + lane]      = s10 * scale;
        sc[qb*SC_PITCH + c*CK + lane + 32] = s11 * scale;
        __syncthreads();
    }

    // ------------ softmax (each warp: 2 rows of 512) ------------
    #pragma unroll
    for (int qq = 0; qq < 2; qq++) {
        const int q = qa + qq;
        float* srow = &sc[q*SC_PITCH];
        float m = -1e30f;
        #pragma unroll
        for (int j = 0; j < 16; j++) m = fmaxf(m, srow[lane + 32*j]);
        #pragma unroll
        for (int o = 16; o; o >>= 1) m = fmaxf(m, __shfl_xor_sync(0xffffffffu, m, o));
        float e[16];
        float s = 0.f;
        #pragma unroll
        for (int j = 0; j < 16; j++) { e[j] = __expf(srow[lane + 32*j] - m); s += e[j]; }
        #pragma unroll
        for (int o = 16; o; o >>= 1) s += __shfl_xor_sync(0xffffffffu, s, o);
        const float r = 1.0f / s;
        float* arow = attn_out + ((size_t)((b*HEADS + h)*SQL + q0t + q))*SKL;
        #pragma unroll
        for (int j = 0; j < 16; j++) {
            float p = e[j] * r;
            srow[lane + 32*j] = p;
            arow[lane + 32*j] = p;
        }
    }
    __syncthreads();

    // ------------ attended = attn @ V ------------
    {
        const int q  = tid >> 4;
        const int dg = (tid & 15) << 2;
        float ax=0.f, ay=0.f, az=0.f, aw=0.f;
        for (int c = 0; c < NCH; c++) {
            #pragma unroll
            for (int it = 0; it < 4; it++) {
                int i  = tid + it*256;
                int kp = i >> 4;
                int d4 = (i & 15) << 2;
                float4 t = *(const float4*)&g_V[((size_t)(b*SKL + c*CK + kp))*EMBED + h*HDIM + d4];
                *(float4*)&kv[kp*KV_PITCH + d4] = t;
            }
            __syncthreads();
            const float* prow = &sc[q*SC_PITCH + c*CK];
            #pragma unroll 8
            for (int kp = 0; kp < CK; kp++) {
                float p = prow[kp];
                float4 vv = *(const float4*)&kv[kp*KV_PITCH + dg];
                ax += p*vv.x; ay += p*vv.y; az += p*vv.z; aw += p*vv.w;
            }
            __syncthreads();
        }
        float4 o; o.x=ax; o.y=ay; o.z=az; o.w=aw;
        *(float4*)&g_att[((size_t)(b*SQL + q0t + q))*EMBED + h*HDIM + dg] = o;
    }
}

// ---------------------------------------------------------------------------
extern "C" void kernel_launch(void* const* d_in, const int* in_sizes, int n_in,
                              void* d_out, int out_size)
{
    (void)in_sizes; (void)n_in; (void)out_size;
    const float* query = (const float*)d_in[0];
    const float* key_  = (const float*)d_in[1];
    const float* value = (const float*)d_in[2];
    const float* Wq = (const float*)d_in[3];
    const float* bq = (const float*)d_in[4];
    const float* Wk = (const float*)d_in[5];
    const float* bk = (const float*)d_in[6];
    const float* Wv = (const float*)d_in[7];
    const float* bv = (const float*)d_in[8];
    const float* vp = (const float*)d_in[9];
    const float* Wo = (const float*)d_in[10];
    const float* bo = (const float*)d_in[11];

    float* out  = (float*)d_out;                 // [B, SQ, EMBED]
    float* attn = out + (size_t)MTOT * EMBED;    // [B, H, SQ, SK]

    float *gQ, *gK, *gV, *gA;
    cudaGetSymbolAddress((void**)&gQ, g_Q);
    cudaGetSymbolAddress((void**)&gK, g_K);
    cudaGetSymbolAddress((void**)&gV, g_V);
    cudaGetSymbolAddress((void**)&gA, g_att);

    const int smem_bytes = ATTN_SMEM_FLOATS * (int)sizeof(float);
    cudaFuncSetAttribute(attn_kernel, cudaFuncAttributeMaxDynamicSharedMemorySize, smem_bytes);

    dim3 ggrid3(EMBED/64, MTOT/64, 3);   // (4, 32, 3)
    gemm_bias3_kernel<<<ggrid3, 256>>>(query, key_, value,
                                       Wq, Wk, Wv,
                                       bq, bk, bv,
                                       gQ, gK, gV,
                                       MTOT, EMBED, EMBED);

    dim3 agrid(SQL/16, HEADS, BATCH);  // (32, 4, 4)
    attn_kernel<<<agrid, 256, smem_bytes>>>(vp, attn);

    dim3 ggrid(EMBED/64, MTOT/64, 1);
    gemm_bias3_kernel<<<ggrid, 256>>>(gA, gA, gA,
                                      Wo, Wo, Wo,
                                      bo, bo, bo,
                                      out, out, out,
                                      MTOT, EMBED, EMBED);
}

// round 5
// speedup vs baseline: 1.1917x; 1.0328x over previous
#include <cuda_runtime.h>
#include <cuda_fp16.h>
#include <cstdint>

#define EMBED 256
#define HEADS 4
#define HDIM  64
#define BATCH 4
#define SQL   512
#define SKL   512
#define MTOT  (BATCH*SQL)   /* 2048 */

// Scratch (allocation-free rule: __device__ globals)
__device__ float g_Q[MTOT*EMBED];
__device__ float g_K[MTOT*EMBED];
__device__ float g_V[MTOT*EMBED];
__device__ float g_att[MTOT*EMBED];

__device__ __forceinline__ __half2 htanh2(__half2 x) {
    unsigned int xi = *reinterpret_cast<unsigned int*>(&x);
    unsigned int yi;
    asm("tanh.approx.f16x2 %0, %1;" : "=r"(yi) : "r"(xi));
    return *reinterpret_cast<__half2*>(&yi);
}

__device__ __forceinline__ float sumh2(__half2 h) {
    float2 f = __half22float2(h);
    return f.x + f.y;
}

// ---------------------------------------------------------------------------
// C[M,N] = A[M,K] @ W[N,K]^T + bias[N]   (torch Linear semantics)
// 64x64 tile, BK=16, 256 threads, 4x4 micro-tile, double-buffered smem.
// grid.z selects one of up to 3 independent (A,W,b,C) problems.
// ---------------------------------------------------------------------------
__global__ __launch_bounds__(256) void gemm_bias3_kernel(
    const float* __restrict__ A0, const float* __restrict__ A1, const float* __restrict__ A2,
    const float* __restrict__ W0, const float* __restrict__ W1, const float* __restrict__ W2,
    const float* __restrict__ b0, const float* __restrict__ b1, const float* __restrict__ b2,
    float* __restrict__ C0, float* __restrict__ C1, float* __restrict__ C2,
    int M, int N, int K)
{
    const float* A; const float* W; const float* bias; float* C;
    if (blockIdx.z == 0)      { A = A0; W = W0; bias = b0; C = C0; }
    else if (blockIdx.z == 1) { A = A1; W = W1; bias = b1; C = C1; }
    else                      { A = A2; W = W2; bias = b2; C = C2; }

    __shared__ float As[2][16][68];
    __shared__ float Ws[2][16][68];
    const int tid = threadIdx.x;
    const int tx  = tid & 15;        // n direction
    const int ty  = tid >> 4;        // m direction
    const int n0  = blockIdx.x * 64;
    const int m0  = blockIdx.y * 64;

    const int lr = tid >> 2;          // 0..63 row in tile
    const int lc = (tid & 3) << 2;    // 0,4,8,12 k offset
    const float* Ag = A + (size_t)(m0 + lr) * K + lc;
    const float* Wg = W + (size_t)(n0 + lr) * K + lc;

    float a00=0,a01=0,a02=0,a03=0, a10=0,a11=0,a12=0,a13=0;
    float a20=0,a21=0,a22=0,a23=0, a30=0,a31=0,a32=0,a33=0;

    float4 av = *(const float4*)(Ag);
    float4 wv = *(const float4*)(Wg);
    int buf = 0;

    for (int k0 = 0; k0 < K; k0 += 16) {
        As[buf][lc+0][lr] = av.x; As[buf][lc+1][lr] = av.y;
        As[buf][lc+2][lr] = av.z; As[buf][lc+3][lr] = av.w;
        Ws[buf][lc+0][lr] = wv.x; Ws[buf][lc+1][lr] = wv.y;
        Ws[buf][lc+2][lr] = wv.z; Ws[buf][lc+3][lr] = wv.w;
        __syncthreads();
        if (k0 + 16 < K) {
            av = *(const float4*)(Ag + k0 + 16);
            wv = *(const float4*)(Wg + k0 + 16);
        }
        #pragma unroll
        for (int k = 0; k < 16; k++) {
            float4 a = *(const float4*)&As[buf][k][ty*4];
            float4 w = *(const float4*)&Ws[buf][k][tx*4];
            a00 += a.x*w.x; a01 += a.x*w.y; a02 += a.x*w.z; a03 += a.x*w.w;
            a10 += a.y*w.x; a11 += a.y*w.y; a12 += a.y*w.z; a13 += a.y*w.w;
            a20 += a.z*w.x; a21 += a.z*w.y; a22 += a.z*w.z; a23 += a.z*w.w;
            a30 += a.w*w.x; a31 += a.w*w.y; a32 += a.w*w.z; a33 += a.w*w.w;
        }
        buf ^= 1;
    }

    const float4 bb = *(const float4*)&bias[n0 + tx*4];
    float* Cp = C + (size_t)(m0 + ty*4) * N + n0 + tx*4;
    float4 o;
    o.x=a00+bb.x; o.y=a01+bb.y; o.z=a02+bb.z; o.w=a03+bb.w; *(float4*)(Cp)       = o;
    o.x=a10+bb.x; o.y=a11+bb.y; o.z=a12+bb.z; o.w=a13+bb.w; *(float4*)(Cp + N)   = o;
    o.x=a20+bb.x; o.y=a21+bb.y; o.z=a22+bb.z; o.w=a23+bb.w; *(float4*)(Cp + 2*N) = o;
    o.x=a30+bb.x; o.y=a31+bb.y; o.z=a32+bb.z; o.w=a33+bb.w; *(float4*)(Cp + 3*N) = o;
}

// ---------------------------------------------------------------------------
// Fused additive-attention kernel, v3: f16x2 tanh for scores.
// Block = (b, h, 16 q-rows), 256 threads (8 warps). Warp w owns q-rows 2w,2w+1.
// Scores: K staged as half, k-major pitch 66 halves (132B -> conflict-free);
//         Q/v staged as half. tanh.approx.f16x2 does 2 d's per op; accumulate
//         in half2 with 2-way split accumulators, combine in f32.
// AV: V staged f32 pitch 68, unchanged.
// Smem floats: sc 16*516 + kv 64*68 (union w/ K-half 64*66*2B) + qh 16*64h + vh 64h
// ---------------------------------------------------------------------------
#define CK 64
#define NCH (SKL/CK)
#define SC_PITCH 516
#define KV_PITCH 68      /* f32 pitch for V   */
#define KH_PITCH 66      /* half pitch for K  */
#define ATTN_SMEM_FLOATS (16*SC_PITCH + CK*KV_PITCH + (16*64)/2 + 32)

__global__ __launch_bounds__(256, 4) void attn_kernel(
    const float* __restrict__ vparam, float* __restrict__ attn_out)
{
    extern __shared__ float smem[];
    float*  sc  = smem;                          // [16][516] scores/probs
    float*  kv  = sc + 16*SC_PITCH;              // [64][68] f32 V chunk
    __half* kvh = (__half*)kv;                   // [64][66] half K chunk (union)
    __half* qh  = (__half*)(kv + CK*KV_PITCH);   // [16][64] half Q
    __half* vh  = qh + 16*64;                    // [64] half v

    const int tid  = threadIdx.x;
    const int lane = tid & 31;
    const int warp = tid >> 5;
    const int b  = blockIdx.z;
    const int h  = blockIdx.y;
    const int q0t = blockIdx.x << 4;

    // stage v[h,:] and the 16 Q rows as half
    if (tid < 64) vh[tid] = __float2half(vparam[h*HDIM + tid]);
    {
        int q  = tid >> 4;
        int dg = (tid & 15) << 2;
        float4 t = *(const float4*)&g_Q[((size_t)(b*SQL + q0t + q))*EMBED + h*HDIM + dg];
        *(__half2*)&qh[q*64 + dg]     = __floats2half2_rn(t.x, t.y);
        *(__half2*)&qh[q*64 + dg + 2] = __floats2half2_rn(t.z, t.w);
    }
    __syncthreads();

    const float scale = 0.125f;   // 1/sqrt(64)
    const int qa = warp*2;        // this warp's two q rows
    const int qb = qa + 1;

    // ------------ scores: 8 chunks of 64 k-rows ------------
    for (int c = 0; c < NCH; c++) {
        // stage K chunk as half, k-major: kvh[kp*66 + d]
        #pragma unroll
        for (int it = 0; it < 4; it++) {
            int i  = tid + it*256;
            int kp = i >> 4;
            int dg = (i & 15) << 2;
            float4 t = *(const float4*)&g_K[((size_t)(b*SKL + c*CK + kp))*EMBED + h*HDIM + dg];
            *(__half2*)&kvh[kp*KH_PITCH + dg]     = __floats2half2_rn(t.x, t.y);
            *(__half2*)&kvh[kp*KH_PITCH + dg + 2] = __floats2half2_rn(t.z, t.w);
        }
        __syncthreads();

        const __half2* kr0 = (const __half2*)&kvh[lane*KH_PITCH];
        const __half2* kr1 = (const __half2*)&kvh[(lane+32)*KH_PITCH];
        const __half2* qav = (const __half2*)&qh[qa*64];
        const __half2* qbv = (const __half2*)&qh[qb*64];
        const __half2* vv2 = (const __half2*)vh;

        __half2 z = __float2half2_rn(0.f);
        __half2 acc00a=z, acc00b=z, acc01a=z, acc01b=z;
        __half2 acc10a=z, acc10b=z, acc11a=z, acc11b=z;

        #pragma unroll 8
        for (int d2 = 0; d2 < 32; d2 += 2) {
            {
                __half2 k0 = kr0[d2], k1 = kr1[d2];
                __half2 qa2 = qav[d2], qb2 = qbv[d2], vv = vv2[d2];
                acc00a = __hfma2(vv, htanh2(__hadd2(qa2, k0)), acc00a);
                acc01a = __hfma2(vv, htanh2(__hadd2(qa2, k1)), acc01a);
                acc10a = __hfma2(vv, htanh2(__hadd2(qb2, k0)), acc10a);
                acc11a = __hfma2(vv, htanh2(__hadd2(qb2, k1)), acc11a);
            }
            {
                __half2 k0 = kr0[d2+1], k1 = kr1[d2+1];
                __half2 qa2 = qav[d2+1], qb2 = qbv[d2+1], vv = vv2[d2+1];
                acc00b = __hfma2(vv, htanh2(__hadd2(qa2, k0)), acc00b);
                acc01b = __hfma2(vv, htanh2(__hadd2(qa2, k1)), acc01b);
                acc10b = __hfma2(vv, htanh2(__hadd2(qb2, k0)), acc10b);
                acc11b = __hfma2(vv, htanh2(__hadd2(qb2, k1)), acc11b);
            }
        }

        sc[qa*SC_PITCH + c*CK + lane]      = (sumh2(acc00a) + sumh2(acc00b)) * scale;
        sc[qa*SC_PITCH + c*CK + lane + 32] = (sumh2(acc01a) + sumh2(acc01b)) * scale;
        sc[qb*SC_PITCH + c*CK + lane]      = (sumh2(acc10a) + sumh2(acc10b)) * scale;
        sc[qb*SC_PITCH + c*CK + lane + 32] = (sumh2(acc11a) + sumh2(acc11b)) * scale;
        __syncthreads();
    }

    // ------------ softmax (each warp: 2 rows of 512) ------------
    #pragma unroll
    for (int qq = 0; qq < 2; qq++) {
        const int q = qa + qq;
        float* srow = &sc[q*SC_PITCH];
        float m = -1e30f;
        #pragma unroll
        for (int j = 0; j < 16; j++) m = fmaxf(m, srow[lane + 32*j]);
        #pragma unroll
        for (int o = 16; o; o >>= 1) m = fmaxf(m, __shfl_xor_sync(0xffffffffu, m, o));
        float e[16];
        float s = 0.f;
        #pragma unroll
        for (int j = 0; j < 16; j++) { e[j] = __expf(srow[lane + 32*j] - m); s += e[j]; }
        #pragma unroll
        for (int o = 16; o; o >>= 1) s += __shfl_xor_sync(0xffffffffu, s, o);
        const float r = 1.0f / s;
        float* arow = attn_out + ((size_t)((b*HEADS + h)*SQL + q0t + q))*SKL;
        #pragma unroll
        for (int j = 0; j < 16; j++) {
            float p = e[j] * r;
            srow[lane + 32*j] = p;
            arow[lane + 32*j] = p;
        }
    }
    __syncthreads();

    // ------------ attended = attn @ V ------------
    {
        const int q  = tid >> 4;
        const int dg = (tid & 15) << 2;
        float ax=0.f, ay=0.f, az=0.f, aw=0.f;
        for (int c = 0; c < NCH; c++) {
            #pragma unroll
            for (int it = 0; it < 4; it++) {
                int i  = tid + it*256;
                int kp = i >> 4;
                int d4 = (i & 15) << 2;
                float4 t = *(const float4*)&g_V[((size_t)(b*SKL + c*CK + kp))*EMBED + h*HDIM + d4];
                *(float4*)&kv[kp*KV_PITCH + d4] = t;
            }
            __syncthreads();
            const float* prow = &sc[q*SC_PITCH + c*CK];
            #pragma unroll 8
            for (int kp = 0; kp < CK; kp++) {
                float p = prow[kp];
                float4 vv = *(const float4*)&kv[kp*KV_PITCH + dg];
                ax += p*vv.x; ay += p*vv.y; az += p*vv.z; aw += p*vv.w;
            }
            __syncthreads();
        }
        float4 o; o.x=ax; o.y=ay; o.z=az; o.w=aw;
        *(float4*)&g_att[((size_t)(b*SQL + q0t + q))*EMBED + h*HDIM + dg] = o;
    }
}

// ---------------------------------------------------------------------------
extern "C" void kernel_launch(void* const* d_in, const int* in_sizes, int n_in,
                              void* d_out, int out_size)
{
    (void)in_sizes; (void)n_in; (void)out_size;
    const float* query = (const float*)d_in[0];
    const float* key_  = (const float*)d_in[1];
    const float* value = (const float*)d_in[2];
    const float* Wq = (const float*)d_in[3];
    const float* bq = (const float*)d_in[4];
    const float* Wk = (const float*)d_in[5];
    const float* bk = (const float*)d_in[6];
    const float* Wv = (const float*)d_in[7];
    const float* bv = (const float*)d_in[8];
    const float* vp = (const float*)d_in[9];
    const float* Wo = (const float*)d_in[10];
    const float* bo = (const float*)d_in[11];

    float* out  = (float*)d_out;                 // [B, SQ, EMBED]
    float* attn = out + (size_t)MTOT * EMBED;    // [B, H, SQ, SK]

    float *gQ, *gK, *gV, *gA;
    cudaGetSymbolAddress((void**)&gQ, g_Q);
    cudaGetSymbolAddress((void**)&gK, g_K);
    cudaGetSymbolAddress((void**)&gV, g_V);
    cudaGetSymbolAddress((void**)&gA, g_att);

    const int smem_bytes = ATTN_SMEM_FLOATS * (int)sizeof(float);
    cudaFuncSetAttribute(attn_kernel, cudaFuncAttributeMaxDynamicSharedMemorySize, smem_bytes);

    dim3 ggrid3(EMBED/64, MTOT/64, 3);   // (4, 32, 3)
    gemm_bias3_kernel<<<ggrid3, 256>>>(query, key_, value,
                                       Wq, Wk, Wv,
                                       bq, bk, bv,
                                       gQ, gK, gV,
                                       MTOT, EMBED, EMBED);

    dim3 agrid(SQL/16, HEADS, BATCH);  // (32, 4, 4)
    attn_kernel<<<agrid, 256, smem_bytes>>>(vp, attn);

    dim3 ggrid(EMBED/64, MTOT/64, 1);
    gemm_bias3_kernel<<<ggrid, 256>>>(gA, gA, gA,
                                      Wo, Wo, Wo,
                                      bo, bo, bo,
                                      out, out, out,
                                      MTOT, EMBED, EMBED);
}

// round 6
// speedup vs baseline: 1.2534x; 1.0518x over previous
#include <cuda_runtime.h>
#include <cuda_fp16.h>
#include <cstdint>

#define EMBED 256
#define HEADS 4
#define HDIM  64
#define BATCH 4
#define SQL   512
#define SKL   512
#define MTOT  (BATCH*SQL)   /* 2048 */

// Scratch (allocation-free rule: __device__ globals)
__device__ float g_Q[MTOT*EMBED];
__device__ float g_K[MTOT*EMBED];
__device__ float g_V[MTOT*EMBED];
__device__ float g_att[MTOT*EMBED];

__device__ __forceinline__ __half2 htanh2(__half2 x) {
    unsigned int xi = *reinterpret_cast<unsigned int*>(&x);
    unsigned int yi;
    asm("tanh.approx.f16x2 %0, %1;" : "=r"(yi) : "r"(xi));
    return *reinterpret_cast<__half2*>(&yi);
}

__device__ __forceinline__ float sumh2(__half2 h) {
    float2 f = __half22float2(h);
    return f.x + f.y;
}

// ---------------------------------------------------------------------------
// C[M,N] = A[M,K] @ W[N,K]^T + bias[N]   (torch Linear semantics)
// 64x64 tile, BK=16, 256 threads, 4x4 micro-tile, double-buffered smem.
// grid.z selects one of up to 3 independent (A,W,b,C) problems.
// ---------------------------------------------------------------------------
__global__ __launch_bounds__(256) void gemm_bias3_kernel(
    const float* __restrict__ A0, const float* __restrict__ A1, const float* __restrict__ A2,
    const float* __restrict__ W0, const float* __restrict__ W1, const float* __restrict__ W2,
    const float* __restrict__ b0, const float* __restrict__ b1, const float* __restrict__ b2,
    float* __restrict__ C0, float* __restrict__ C1, float* __restrict__ C2,
    int M, int N, int K)
{
    const float* A; const float* W; const float* bias; float* C;
    if (blockIdx.z == 0)      { A = A0; W = W0; bias = b0; C = C0; }
    else if (blockIdx.z == 1) { A = A1; W = W1; bias = b1; C = C1; }
    else                      { A = A2; W = W2; bias = b2; C = C2; }

    __shared__ float As[2][16][68];
    __shared__ float Ws[2][16][68];
    const int tid = threadIdx.x;
    const int tx  = tid & 15;        // n direction
    const int ty  = tid >> 4;        // m direction
    const int n0  = blockIdx.x * 64;
    const int m0  = blockIdx.y * 64;

    const int lr = tid >> 2;          // 0..63 row in tile
    const int lc = (tid & 3) << 2;    // 0,4,8,12 k offset
    const float* Ag = A + (size_t)(m0 + lr) * K + lc;
    const float* Wg = W + (size_t)(n0 + lr) * K + lc;

    float a00=0,a01=0,a02=0,a03=0, a10=0,a11=0,a12=0,a13=0;
    float a20=0,a21=0,a22=0,a23=0, a30=0,a31=0,a32=0,a33=0;

    float4 av = *(const float4*)(Ag);
    float4 wv = *(const float4*)(Wg);
    int buf = 0;

    for (int k0 = 0; k0 < K; k0 += 16) {
        As[buf][lc+0][lr] = av.x; As[buf][lc+1][lr] = av.y;
        As[buf][lc+2][lr] = av.z; As[buf][lc+3][lr] = av.w;
        Ws[buf][lc+0][lr] = wv.x; Ws[buf][lc+1][lr] = wv.y;
        Ws[buf][lc+2][lr] = wv.z; Ws[buf][lc+3][lr] = wv.w;
        __syncthreads();
        if (k0 + 16 < K) {
            av = *(const float4*)(Ag + k0 + 16);
            wv = *(const float4*)(Wg + k0 + 16);
        }
        #pragma unroll
        for (int k = 0; k < 16; k++) {
            float4 a = *(const float4*)&As[buf][k][ty*4];
            float4 w = *(const float4*)&Ws[buf][k][tx*4];
            a00 += a.x*w.x; a01 += a.x*w.y; a02 += a.x*w.z; a03 += a.x*w.w;
            a10 += a.y*w.x; a11 += a.y*w.y; a12 += a.y*w.z; a13 += a.y*w.w;
            a20 += a.z*w.x; a21 += a.z*w.y; a22 += a.z*w.z; a23 += a.z*w.w;
            a30 += a.w*w.x; a31 += a.w*w.y; a32 += a.w*w.z; a33 += a.w*w.w;
        }
        buf ^= 1;
    }

    const float4 bb = *(const float4*)&bias[n0 + tx*4];
    float* Cp = C + (size_t)(m0 + ty*4) * N + n0 + tx*4;
    float4 o;
    o.x=a00+bb.x; o.y=a01+bb.y; o.z=a02+bb.z; o.w=a03+bb.w; *(float4*)(Cp)       = o;
    o.x=a10+bb.x; o.y=a11+bb.y; o.z=a12+bb.z; o.w=a13+bb.w; *(float4*)(Cp + N)   = o;
    o.x=a20+bb.x; o.y=a21+bb.y; o.z=a22+bb.z; o.w=a23+bb.w; *(float4*)(Cp + 2*N) = o;
    o.x=a30+bb.x; o.y=a31+bb.y; o.z=a32+bb.z; o.w=a33+bb.w; *(float4*)(Cp + 3*N) = o;
}

// ---------------------------------------------------------------------------
// Fused additive-attention kernel, v4: transposed prob buffer for AV.
// Block = (b, h, 16 q-rows), 256 threads (8 warps). Warp w owns q-rows 2w,2w+1
// for scores/softmax; for AV, warp w owns d-slice [8w, 8w+8).
// scT[k][q]: k-major scores/probs, pitch 20 floats (float4-aligned).
// Smem floats: scT 512*20 + kv 64*68 (union w/ K-half 64*66*2B) + qh + vh
//            = 10240 + 4352 + 512 + 32 = 15136 floats = 60544 B -> 3 blocks/SM
// ---------------------------------------------------------------------------
#define CK 64
#define NCH (SKL/CK)
#define SCT_PITCH 20
#define KV_PITCH 68      /* f32 pitch for V   */
#define KH_PITCH 66      /* half pitch for K  */
#define ATTN_SMEM_FLOATS (SKL*SCT_PITCH + CK*KV_PITCH + (16*64)/2 + 32)

__global__ __launch_bounds__(256, 3) void attn_kernel(
    const float* __restrict__ vparam, float* __restrict__ attn_out)
{
    extern __shared__ float smem[];
    float*  scT = smem;                           // [512][20] scores/probs, k-major
    float*  kv  = scT + SKL*SCT_PITCH;            // [64][68] f32 V chunk
    __half* kvh = (__half*)kv;                    // [64][66] half K chunk (union)
    __half* qh  = (__half*)(kv + CK*KV_PITCH);    // [16][64] half Q
    __half* vh  = qh + 16*64;                     // [64] half v

    const int tid  = threadIdx.x;
    const int lane = tid & 31;
    const int warp = tid >> 5;
    const int b  = blockIdx.z;
    const int h  = blockIdx.y;
    const int q0t = blockIdx.x << 4;

    // stage v[h,:] and the 16 Q rows as half
    if (tid < 64) vh[tid] = __float2half(vparam[h*HDIM + tid]);
    {
        int q  = tid >> 4;
        int dg = (tid & 15) << 2;
        float4 t = *(const float4*)&g_Q[((size_t)(b*SQL + q0t + q))*EMBED + h*HDIM + dg];
        *(__half2*)&qh[q*64 + dg]     = __floats2half2_rn(t.x, t.y);
        *(__half2*)&qh[q*64 + dg + 2] = __floats2half2_rn(t.z, t.w);
    }
    __syncthreads();

    const float scale = 0.125f;   // 1/sqrt(64)
    const int qa = warp*2;        // this warp's two q rows (scores/softmax)
    const int qb = qa + 1;

    // ------------ scores: 8 chunks of 64 k-rows ------------
    for (int c = 0; c < NCH; c++) {
        // stage K chunk as half, k-major: kvh[kp*66 + d]
        #pragma unroll
        for (int it = 0; it < 4; it++) {
            int i  = tid + it*256;
            int kp = i >> 4;
            int dg = (i & 15) << 2;
            float4 t = *(const float4*)&g_K[((size_t)(b*SKL + c*CK + kp))*EMBED + h*HDIM + dg];
            *(__half2*)&kvh[kp*KH_PITCH + dg]     = __floats2half2_rn(t.x, t.y);
            *(__half2*)&kvh[kp*KH_PITCH + dg + 2] = __floats2half2_rn(t.z, t.w);
        }
        __syncthreads();

        const __half2* kr0 = (const __half2*)&kvh[lane*KH_PITCH];
        const __half2* kr1 = (const __half2*)&kvh[(lane+32)*KH_PITCH];
        const __half2* qav = (const __half2*)&qh[qa*64];
        const __half2* qbv = (const __half2*)&qh[qb*64];
        const __half2* vv2 = (const __half2*)vh;

        __half2 z = __float2half2_rn(0.f);
        __half2 acc00a=z, acc00b=z, acc01a=z, acc01b=z;
        __half2 acc10a=z, acc10b=z, acc11a=z, acc11b=z;

        #pragma unroll 8
        for (int d2 = 0; d2 < 32; d2 += 2) {
            {
                __half2 k0 = kr0[d2], k1 = kr1[d2];
                __half2 qa2 = qav[d2], qb2 = qbv[d2], vv = vv2[d2];
                acc00a = __hfma2(vv, htanh2(__hadd2(qa2, k0)), acc00a);
                acc01a = __hfma2(vv, htanh2(__hadd2(qa2, k1)), acc01a);
                acc10a = __hfma2(vv, htanh2(__hadd2(qb2, k0)), acc10a);
                acc11a = __hfma2(vv, htanh2(__hadd2(qb2, k1)), acc11a);
            }
            {
                __half2 k0 = kr0[d2+1], k1 = kr1[d2+1];
                __half2 qa2 = qav[d2+1], qb2 = qbv[d2+1], vv = vv2[d2+1];
                acc00b = __hfma2(vv, htanh2(__hadd2(qa2, k0)), acc00b);
                acc01b = __hfma2(vv, htanh2(__hadd2(qa2, k1)), acc01b);
                acc10b = __hfma2(vv, htanh2(__hadd2(qb2, k0)), acc10b);
                acc11b = __hfma2(vv, htanh2(__hadd2(qb2, k1)), acc11b);
            }
        }

        // scT[k][q], k = c*CK + lane (+32)
        scT[(c*CK + lane)      * SCT_PITCH + qa] = (sumh2(acc00a) + sumh2(acc00b)) * scale;
        scT[(c*CK + lane + 32) * SCT_PITCH + qa] = (sumh2(acc01a) + sumh2(acc01b)) * scale;
        scT[(c*CK + lane)      * SCT_PITCH + qb] = (sumh2(acc10a) + sumh2(acc10b)) * scale;
        scT[(c*CK + lane + 32) * SCT_PITCH + qb] = (sumh2(acc11a) + sumh2(acc11b)) * scale;
        __syncthreads();
    }

    // ------------ softmax (each warp: 2 rows of 512; column q of scT) ------------
    #pragma unroll
    for (int qq = 0; qq < 2; qq++) {
        const int q = qa + qq;
        float m = -1e30f;
        #pragma unroll
        for (int j = 0; j < 16; j++) m = fmaxf(m, scT[(lane + 32*j)*SCT_PITCH + q]);
        #pragma unroll
        for (int o = 16; o; o >>= 1) m = fmaxf(m, __shfl_xor_sync(0xffffffffu, m, o));
        float e[16];
        float s = 0.f;
        #pragma unroll
        for (int j = 0; j < 16; j++) { e[j] = __expf(scT[(lane + 32*j)*SCT_PITCH + q] - m); s += e[j]; }
        #pragma unroll
        for (int o = 16; o; o >>= 1) s += __shfl_xor_sync(0xffffffffu, s, o);
        const float r = 1.0f / s;
        float* arow = attn_out + ((size_t)((b*HEADS + h)*SQL + q0t + q))*SKL;
        #pragma unroll
        for (int j = 0; j < 16; j++) {
            float p = e[j] * r;
            scT[(lane + 32*j)*SCT_PITCH + q] = p;
            arow[lane + 32*j] = p;
        }
    }
    __syncthreads();

    // ------------ attended = attn @ V ------------
    // lane -> q-group g = lane>>3 (q = 4g..4g+3), d = warp*8 + (lane&7)
    {
        const int g  = lane >> 3;
        const int dl = warp*8 + (lane & 7);
        float a0=0.f, a1=0.f, a2=0.f, a3=0.f;
        for (int c = 0; c < NCH; c++) {
            #pragma unroll
            for (int it = 0; it < 4; it++) {
                int i  = tid + it*256;
                int kp = i >> 4;
                int d4 = (i & 15) << 2;
                float4 t = *(const float4*)&g_V[((size_t)(b*SKL + c*CK + kp))*EMBED + h*HDIM + d4];
                *(float4*)&kv[kp*KV_PITCH + d4] = t;
            }
            __syncthreads();
            const float* pbase = &scT[(c*CK)*SCT_PITCH + 4*g];
            const float* vbase = &kv[dl];
            #pragma unroll 8
            for (int kp = 0; kp < CK; kp++) {
                float4 p = *(const float4*)(pbase + kp*SCT_PITCH);
                float  v = vbase[kp*KV_PITCH];
                a0 += p.x*v; a1 += p.y*v; a2 += p.z*v; a3 += p.w*v;
            }
            __syncthreads();
        }
        float* abase = &g_att[((size_t)(b*SQL + q0t + 4*g))*EMBED + h*HDIM + dl];
        abase[0]       = a0;
        abase[EMBED]   = a1;
        abase[2*EMBED] = a2;
        abase[3*EMBED] = a3;
    }
}

// ---------------------------------------------------------------------------
extern "C" void kernel_launch(void* const* d_in, const int* in_sizes, int n_in,
                              void* d_out, int out_size)
{
    (void)in_sizes; (void)n_in; (void)out_size;
    const float* query = (const float*)d_in[0];
    const float* key_  = (const float*)d_in[1];
    const float* value = (const float*)d_in[2];
    const float* Wq = (const float*)d_in[3];
    const float* bq = (const float*)d_in[4];
    const float* Wk = (const float*)d_in[5];
    const float* bk = (const float*)d_in[6];
    const float* Wv = (const float*)d_in[7];
    const float* bv = (const float*)d_in[8];
    const float* vp = (const float*)d_in[9];
    const float* Wo = (const float*)d_in[10];
    const float* bo = (const float*)d_in[11];

    float* out  = (float*)d_out;                 // [B, SQ, EMBED]
    float* attn = out + (size_t)MTOT * EMBED;    // [B, H, SQ, SK]

    float *gQ, *gK, *gV, *gA;
    cudaGetSymbolAddress((void**)&gQ, g_Q);
    cudaGetSymbolAddress((void**)&gK, g_K);
    cudaGetSymbolAddress((void**)&gV, g_V);
    cudaGetSymbolAddress((void**)&gA, g_att);

    const int smem_bytes = ATTN_SMEM_FLOATS * (int)sizeof(float);
    cudaFuncSetAttribute(attn_kernel, cudaFuncAttributeMaxDynamicSharedMemorySize, smem_bytes);

    dim3 ggrid3(EMBED/64, MTOT/64, 3);   // (4, 32, 3)
    gemm_bias3_kernel<<<ggrid3, 256>>>(query, key_, value,
                                       Wq, Wk, Wv,
                                       bq, bk, bv,
                                       gQ, gK, gV,
                                       MTOT, EMBED, EMBED);

    dim3 agrid(SQL/16, HEADS, BATCH);  // (32, 4, 4)
    attn_kernel<<<agrid, 256, smem_bytes>>>(vp, attn);

    dim3 ggrid(EMBED/64, MTOT/64, 1);
    gemm_bias3_kernel<<<ggrid, 256>>>(gA, gA, gA,
                                      Wo, Wo, Wo,
                                      bo, bo, bo,
                                      out, out, out,
                                      MTOT, EMBED, EMBED);
}

// round 7
// speedup vs baseline: 1.2979x; 1.0355x over previous
#include <cuda_runtime.h>
#include <cuda_fp16.h>
#include <cstdint>

#define EMBED 256
#define HEADS 4
#define HDIM  64
#define BATCH 4
#define SQL   512
#define SKL   512
#define MTOT  (BATCH*SQL)   /* 2048 */

// Scratch (allocation-free rule: __device__ globals)
__device__ float g_Q[MTOT*EMBED];
__device__ float g_K[MTOT*EMBED];
__device__ float g_V[MTOT*EMBED];
__device__ float g_att[MTOT*EMBED];

__device__ __forceinline__ __half2 htanh2(__half2 x) {
    unsigned int xi = *reinterpret_cast<unsigned int*>(&x);
    unsigned int yi;
    asm("tanh.approx.f16x2 %0, %1;" : "=r"(yi) : "r"(xi));
    return *reinterpret_cast<__half2*>(&yi);
}

__device__ __forceinline__ float sumh2(__half2 h) {
    float2 f = __half22float2(h);
    return f.x + f.y;
}

__device__ __forceinline__ __half2 u2h(unsigned int u) {
    return *reinterpret_cast<__half2*>(&u);
}

// ---------------------------------------------------------------------------
// C[M,N] = A[M,K] @ W[N,K]^T + bias[N]   (torch Linear semantics)
// 64x64 tile, BK=16, 256 threads, 4x4 micro-tile, double-buffered smem.
// grid.z selects one of up to 3 independent (A,W,b,C) problems.
// ---------------------------------------------------------------------------
__global__ __launch_bounds__(256) void gemm_bias3_kernel(
    const float* __restrict__ A0, const float* __restrict__ A1, const float* __restrict__ A2,
    const float* __restrict__ W0, const float* __restrict__ W1, const float* __restrict__ W2,
    const float* __restrict__ b0, const float* __restrict__ b1, const float* __restrict__ b2,
    float* __restrict__ C0, float* __restrict__ C1, float* __restrict__ C2,
    int M, int N, int K)
{
    const float* A; const float* W; const float* bias; float* C;
    if (blockIdx.z == 0)      { A = A0; W = W0; bias = b0; C = C0; }
    else if (blockIdx.z == 1) { A = A1; W = W1; bias = b1; C = C1; }
    else                      { A = A2; W = W2; bias = b2; C = C2; }

    __shared__ float As[2][16][68];
    __shared__ float Ws[2][16][68];
    const int tid = threadIdx.x;
    const int tx  = tid & 15;        // n direction
    const int ty  = tid >> 4;        // m direction
    const int n0  = blockIdx.x * 64;
    const int m0  = blockIdx.y * 64;

    const int lr = tid >> 2;          // 0..63 row in tile
    const int lc = (tid & 3) << 2;    // 0,4,8,12 k offset
    const float* Ag = A + (size_t)(m0 + lr) * K + lc;
    const float* Wg = W + (size_t)(n0 + lr) * K + lc;

    float a00=0,a01=0,a02=0,a03=0, a10=0,a11=0,a12=0,a13=0;
    float a20=0,a21=0,a22=0,a23=0, a30=0,a31=0,a32=0,a33=0;

    float4 av = *(const float4*)(Ag);
    float4 wv = *(const float4*)(Wg);
    int buf = 0;

    for (int k0 = 0; k0 < K; k0 += 16) {
        As[buf][lc+0][lr] = av.x; As[buf][lc+1][lr] = av.y;
        As[buf][lc+2][lr] = av.z; As[buf][lc+3][lr] = av.w;
        Ws[buf][lc+0][lr] = wv.x; Ws[buf][lc+1][lr] = wv.y;
        Ws[buf][lc+2][lr] = wv.z; Ws[buf][lc+3][lr] = wv.w;
        __syncthreads();
        if (k0 + 16 < K) {
            av = *(const float4*)(Ag + k0 + 16);
            wv = *(const float4*)(Wg + k0 + 16);
        }
        #pragma unroll
        for (int k = 0; k < 16; k++) {
            float4 a = *(const float4*)&As[buf][k][ty*4];
            float4 w = *(const float4*)&Ws[buf][k][tx*4];
            a00 += a.x*w.x; a01 += a.x*w.y; a02 += a.x*w.z; a03 += a.x*w.w;
            a10 += a.y*w.x; a11 += a.y*w.y; a12 += a.y*w.z; a13 += a.y*w.w;
            a20 += a.z*w.x; a21 += a.z*w.y; a22 += a.z*w.z; a23 += a.z*w.w;
            a30 += a.w*w.x; a31 += a.w*w.y; a32 += a.w*w.z; a33 += a.w*w.w;
        }
        buf ^= 1;
    }

    const float4 bb = *(const float4*)&bias[n0 + tx*4];
    float* Cp = C + (size_t)(m0 + ty*4) * N + n0 + tx*4;
    float4 o;
    o.x=a00+bb.x; o.y=a01+bb.y; o.z=a02+bb.z; o.w=a03+bb.w; *(float4*)(Cp)       = o;
    o.x=a10+bb.x; o.y=a11+bb.y; o.z=a12+bb.z; o.w=a13+bb.w; *(float4*)(Cp + N)   = o;
    o.x=a20+bb.x; o.y=a21+bb.y; o.z=a22+bb.z; o.w=a23+bb.w; *(float4*)(Cp + 2*N) = o;
    o.x=a30+bb.x; o.y=a31+bb.y; o.z=a32+bb.z; o.w=a33+bb.w; *(float4*)(Cp + 3*N) = o;
}

// ---------------------------------------------------------------------------
// Fused additive-attention kernel, v5:
//  * 4 blocks/SM (51.8KB smem) -> single wave for grid 512
//  * register-prefetch software pipeline for K and V staging
//  * vectorized score loads: 3x LDS.128 bcast + 4x LDS.64 per 16 MUFU
// Block = (b, h, 16 q-rows), 256 threads (8 warps).
// Scores/softmax: warp w owns q-rows 2w,2w+1. AV: warp w owns d [8w,8w+8).
// Smem floats: scT 512*20 + union(K-half 64*68h, V-f32 32*68f)=2176 + qh 512 + vh 32
// ---------------------------------------------------------------------------
#define CK 64
#define NCHK (SKL/CK)     /* 8  */
#define CKV 32
#define NCHV (SKL/CKV)    /* 16 */
#define SCT_PITCH 20
#define KH_PITCH 68       /* halves */
#define VF_PITCH 68       /* floats */
#define UNION_FLOATS 2176 /* max(64*68*2B, 32*68*4B) = 8704B */
#define ATTN_SMEM_FLOATS (SKL*SCT_PITCH + UNION_FLOATS + 512 + 32)

__global__ __launch_bounds__(256, 4) void attn_kernel(
    const float* __restrict__ vparam, float* __restrict__ attn_out)
{
    extern __shared__ float smem[];
    float*  scT = smem;                           // [512][20] scores/probs, k-major
    float*  kvf = scT + SKL*SCT_PITCH;            // [32][68] f32 V chunk (union)
    __half* kvh = (__half*)kvf;                   // [64][68] half K chunk (union)
    __half* qh  = (__half*)(kvf + UNION_FLOATS);  // [16][64] half Q
    __half* vh  = qh + 16*64;                     // [64] half v

    const int tid  = threadIdx.x;
    const int lane = tid & 31;
    const int warp = tid >> 5;
    const int b  = blockIdx.z;
    const int h  = blockIdx.y;
    const int q0t = blockIdx.x << 4;

    const int kp16 = tid >> 4;           // staging row 0..15
    const int dg16 = (tid & 15) << 2;    // staging d offset 0,4,..,60

    // stage v[h,:] and the 16 Q rows as half
    if (tid < 64) vh[tid] = __float2half(vparam[h*HDIM + tid]);
    {
        float4 t = *(const float4*)&g_Q[((size_t)(b*SQL + q0t + kp16))*EMBED + h*HDIM + dg16];
        __half2 h0 = __floats2half2_rn(t.x, t.y);
        __half2 h1 = __floats2half2_rn(t.z, t.w);
        unsigned int u0 = *(unsigned int*)&h0, u1 = *(unsigned int*)&h1;
        *(uint2*)&qh[kp16*64 + dg16] = make_uint2(u0, u1);
    }

    const float scale = 0.125f;   // 1/sqrt(64)
    const int qa = warp*2;        // this warp's two q rows (scores/softmax)
    const int qb = qa + 1;

    // ---------------- score phase: 8 chunks of 64 k-rows, pipelined ----------
    float4 kpre[4];
    const float* Kbase = &g_K[((size_t)(b*SKL))*EMBED + h*HDIM + dg16];

    // prime chunk 0
    #pragma unroll
    for (int it = 0; it < 4; it++) {
        int kp = kp16 + it*16;
        kpre[it] = *(const float4*)(Kbase + (size_t)(kp)*EMBED);
    }
    #pragma unroll
    for (int it = 0; it < 4; it++) {
        int kp = kp16 + it*16;
        __half2 h0 = __floats2half2_rn(kpre[it].x, kpre[it].y);
        __half2 h1 = __floats2half2_rn(kpre[it].z, kpre[it].w);
        *(uint2*)&kvh[kp*KH_PITCH + dg16] = make_uint2(*(unsigned int*)&h0, *(unsigned int*)&h1);
    }
    __syncthreads();

    for (int c = 0; c < NCHK; c++) {
        if (c + 1 < NCHK) {
            #pragma unroll
            for (int it = 0; it < 4; it++) {
                int kp = (c+1)*CK + kp16 + it*16;
                kpre[it] = *(const float4*)(Kbase + (size_t)(kp)*EMBED);
            }
        }

        const uint4* qa4p = (const uint4*)&qh[qa*64];
        const uint4* qb4p = (const uint4*)&qh[qb*64];
        const uint4* vv4p = (const uint4*)vh;
        const uint2* k0p  = (const uint2*)&kvh[lane*KH_PITCH];
        const uint2* k1p  = (const uint2*)&kvh[(lane+32)*KH_PITCH];

        __half2 z = __float2half2_rn(0.f);
        __half2 acc00a=z, acc00b=z, acc01a=z, acc01b=z;
        __half2 acc10a=z, acc10b=z, acc11a=z, acc11b=z;

        #pragma unroll
        for (int db = 0; db < 8; db++) {
            uint4 qa4 = qa4p[db];
            uint4 qb4 = qb4p[db];
            uint4 vv4 = vv4p[db];
            uint2 k0lo = k0p[db*2], k0hi = k0p[db*2+1];
            uint2 k1lo = k1p[db*2], k1hi = k1p[db*2+1];

            __half2 qa0=u2h(qa4.x), qa1=u2h(qa4.y), qa2=u2h(qa4.z), qa3=u2h(qa4.w);
            __half2 qb0=u2h(qb4.x), qb1=u2h(qb4.y), qb2=u2h(qb4.z), qb3=u2h(qb4.w);
            __half2 vv0=u2h(vv4.x), vv1=u2h(vv4.y), vv2=u2h(vv4.z), vv3=u2h(vv4.w);
            __half2 k00=u2h(k0lo.x), k01=u2h(k0lo.y), k02=u2h(k0hi.x), k03=u2h(k0hi.y);
            __half2 k10=u2h(k1lo.x), k11=u2h(k1lo.y), k12=u2h(k1hi.x), k13=u2h(k1hi.y);

            acc00a = __hfma2(vv0, htanh2(__hadd2(qa0, k00)), acc00a);
            acc01a = __hfma2(vv0, htanh2(__hadd2(qa0, k10)), acc01a);
            acc10a = __hfma2(vv0, htanh2(__hadd2(qb0, k00)), acc10a);
            acc11a = __hfma2(vv0, htanh2(__hadd2(qb0, k10)), acc11a);

            acc00b = __hfma2(vv1, htanh2(__hadd2(qa1, k01)), acc00b);
            acc01b = __hfma2(vv1, htanh2(__hadd2(qa1, k11)), acc01b);
            acc10b = __hfma2(vv1, htanh2(__hadd2(qb1, k01)), acc10b);
            acc11b = __hfma2(vv1, htanh2(__hadd2(qb1, k11)), acc11b);

            acc00a = __hfma2(vv2, htanh2(__hadd2(qa2, k02)), acc00a);
            acc01a = __hfma2(vv2, htanh2(__hadd2(qa2, k12)), acc01a);
            acc10a = __hfma2(vv2, htanh2(__hadd2(qb2, k02)), acc10a);
            acc11a = __hfma2(vv2, htanh2(__hadd2(qb2, k12)), acc11a);

            acc00b = __hfma2(vv3, htanh2(__hadd2(qa3, k03)), acc00b);
            acc01b = __hfma2(vv3, htanh2(__hadd2(qa3, k13)), acc01b);
            acc10b = __hfma2(vv3, htanh2(__hadd2(qb3, k03)), acc10b);
            acc11b = __hfma2(vv3, htanh2(__hadd2(qb3, k13)), acc11b);
        }

        scT[(c*CK + lane)      * SCT_PITCH + qa] = (sumh2(acc00a) + sumh2(acc00b)) * scale;
        scT[(c*CK + lane + 32) * SCT_PITCH + qa] = (sumh2(acc01a) + sumh2(acc01b)) * scale;
        scT[(c*CK + lane)      * SCT_PITCH + qb] = (sumh2(acc10a) + sumh2(acc10b)) * scale;
        scT[(c*CK + lane + 32) * SCT_PITCH + qb] = (sumh2(acc11a) + sumh2(acc11b)) * scale;

        __syncthreads();   // all reads of kvh + score writes done

        if (c + 1 < NCHK) {
            #pragma unroll
            for (int it = 0; it < 4; it++) {
                int kp = kp16 + it*16;
                __half2 h0 = __floats2half2_rn(kpre[it].x, kpre[it].y);
                __half2 h1 = __floats2half2_rn(kpre[it].z, kpre[it].w);
                *(uint2*)&kvh[kp*KH_PITCH + dg16] = make_uint2(*(unsigned int*)&h0, *(unsigned int*)&h1);
            }
            __syncthreads();
        }
    }

    // ---------------- softmax (each warp: 2 rows of 512) ----------------
    #pragma unroll
    for (int qq = 0; qq < 2; qq++) {
        const int q = qa + qq;
        float x[16];
        #pragma unroll
        for (int j = 0; j < 16; j++) x[j] = scT[(lane + 32*j)*SCT_PITCH + q];
        float m = -1e30f;
        #pragma unroll
        for (int j = 0; j < 16; j++) m = fmaxf(m, x[j]);
        #pragma unroll
        for (int o = 16; o; o >>= 1) m = fmaxf(m, __shfl_xor_sync(0xffffffffu, m, o));
        float s = 0.f;
        #pragma unroll
        for (int j = 0; j < 16; j++) { x[j] = __expf(x[j] - m); s += x[j]; }
        #pragma unroll
        for (int o = 16; o; o >>= 1) s += __shfl_xor_sync(0xffffffffu, s, o);
        const float r = 1.0f / s;
        float* arow = attn_out + ((size_t)((b*HEADS + h)*SQL + q0t + q))*SKL;
        #pragma unroll
        for (int j = 0; j < 16; j++) {
            float p = x[j] * r;
            scT[(lane + 32*j)*SCT_PITCH + q] = p;
            arow[lane + 32*j] = p;
        }
    }
    __syncthreads();

    // ---------------- attended = attn @ V, 16 chunks of 32, pipelined ------
    {
        const int g  = lane >> 3;            // q-group: q = 4g..4g+3
        const int dl = warp*8 + (lane & 7);  // this thread's d
        const int kp32 = tid >> 4;           // staging row 0..15 (it adds 16)
        const float* Vbase = &g_V[((size_t)(b*SKL))*EMBED + h*HDIM + dg16];

        float4 vpre[2];
        #pragma unroll
        for (int it = 0; it < 2; it++) {
            int kp = kp32 + it*16;
            vpre[it] = *(const float4*)(Vbase + (size_t)(kp)*EMBED);
        }
        #pragma unroll
        for (int it = 0; it < 2; it++) {
            int kp = kp32 + it*16;
            *(float4*)&kvf[kp*VF_PITCH + dg16] = vpre[it];
        }
        __syncthreads();

        float a0=0.f, a1=0.f, a2=0.f, a3=0.f;
        for (int c = 0; c < NCHV; c++) {
            if (c + 1 < NCHV) {
                #pragma unroll
                for (int it = 0; it < 2; it++) {
                    int kp = (c+1)*CKV + kp32 + it*16;
                    vpre[it] = *(const float4*)(Vbase + (size_t)(kp)*EMBED);
                }
            }
            const float* pb = &scT[(c*CKV)*SCT_PITCH + 4*g];
            const float* vb = &kvf[dl];
            #pragma unroll 8
            for (int kp = 0; kp < CKV; kp++) {
                float4 p = *(const float4*)(pb + kp*SCT_PITCH);
                float  v = vb[kp*VF_PITCH];
                a0 += p.x*v; a1 += p.y*v; a2 += p.z*v; a3 += p.w*v;
            }
            __syncthreads();
            if (c + 1 < NCHV) {
                #pragma unroll
                for (int it = 0; it < 2; it++) {
                    int kp = kp32 + it*16;
                    *(float4*)&kvf[kp*VF_PITCH + dg16] = vpre[it];
                }
                __syncthreads();
            }
        }

        float* abase = &g_att[((size_t)(b*SQL + q0t + 4*g))*EMBED + h*HDIM + dl];
        abase[0]       = a0;
        abase[EMBED]   = a1;
        abase[2*EMBED] = a2;
        abase[3*EMBED] = a3;
    }
}

// ---------------------------------------------------------------------------
extern "C" void kernel_launch(void* const* d_in, const int* in_sizes, int n_in,
                              void* d_out, int out_size)
{
    (void)in_sizes; (void)n_in; (void)out_size;
    const float* query = (const float*)d_in[0];
    const float* key_  = (const float*)d_in[1];
    const float* value = (const float*)d_in[2];
    const float* Wq = (const float*)d_in[3];
    const float* bq = (const float*)d_in[4];
    const float* Wk = (const float*)d_in[5];
    const float* bk = (const float*)d_in[6];
    const float* Wv = (const float*)d_in[7];
    const float* bv = (const float*)d_in[8];
    const float* vp = (const float*)d_in[9];
    const float* Wo = (const float*)d_in[10];
    const float* bo = (const float*)d_in[11];

    float* out  = (float*)d_out;                 // [B, SQ, EMBED]
    float* attn = out + (size_t)MTOT * EMBED;    // [B, H, SQ, SK]

    float *gQ, *gK, *gV, *gA;
    cudaGetSymbolAddress((void**)&gQ, g_Q);
    cudaGetSymbolAddress((void**)&gK, g_K);
    cudaGetSymbolAddress((void**)&gV, g_V);
    cudaGetSymbolAddress((void**)&gA, g_att);

    const int smem_bytes = ATTN_SMEM_FLOATS * (int)sizeof(float);
    cudaFuncSetAttribute(attn_kernel, cudaFuncAttributeMaxDynamicSharedMemorySize, smem_bytes);

    dim3 ggrid3(EMBED/64, MTOT/64, 3);   // (4, 32, 3)
    gemm_bias3_kernel<<<ggrid3, 256>>>(query, key_, value,
                                       Wq, Wk, Wv,
                                       bq, bk, bv,
                                       gQ, gK, gV,
                                       MTOT, EMBED, EMBED);

    dim3 agrid(SQL/16, HEADS, BATCH);  // (32, 4, 4)
    attn_kernel<<<agrid, 256, smem_bytes>>>(vp, attn);

    dim3 ggrid(EMBED/64, MTOT/64, 1);
    gemm_bias3_kernel<<<ggrid, 256>>>(gA, gA, gA,
                                      Wo, Wo, Wo,
                                      bo, bo, bo,
                                      out, out, out,
                                      MTOT, EMBED, EMBED);
}